// round 4
// baseline (speedup 1.0000x reference)
#include <cuda_runtime.h>

#define NFSZ 1001
#define HSZ   256
#define BSZ   64
#define FD    128
#define INCH  16
#define G4    1024   // 4*H
#define INS0  144    // FD + INCH

// scratch (device globals: allocation-free rule)
__device__ float g_Wt[FD * G4];     // transposed f-part of W_ih0: [k][g]
__device__ float g_Gf[NFSZ * G4];   // pre-scaled f-side gate pre-activations

__device__ __forceinline__ float ex2f(float x) {
    float y; asm("ex2.approx.f32 %0, %1;" : "=f"(y) : "f"(x)); return y;
}
__device__ __forceinline__ float rcpf(float x) {
    float y; asm("rcp.approx.f32 %0, %1;" : "=f"(y) : "f"(x)); return y;
}
__device__ __forceinline__ float negabsf(float x) {   // -|x| : one LOP3
    return __int_as_float(__float_as_int(x) | 0x80000000);
}

// ---------------- precompute kernels ----------------

__global__ void transpose_kernel(const float* __restrict__ Wih0) {
    int idx = blockIdx.x * blockDim.x + threadIdx.x;   // 131072 total
    if (idx >= FD * G4) return;
    int g = idx / FD;
    int k = idx - g * FD;
    g_Wt[k * G4 + g] = Wih0[g * INS0 + k];
}

// Gf[t][g] = scale(g) * sum_k f[t,k] * Wih0[g,k],  scale folds -log2e (-2log2e for g-gate)
__global__ void gf_kernel(const float* __restrict__ f) {
    __shared__ float fs[8][FD];
    int tx = threadIdx.x;                   // 256
    int g  = blockIdx.y * 256 + tx;
    int t0 = blockIdx.x * 8;
    #pragma unroll
    for (int i = 0; i < 4; i++) {
        int e  = tx + i * 256;
        int tt = e >> 7, kk = e & 127;
        int t  = t0 + tt;
        fs[tt][kk] = (t < NFSZ) ? f[t * FD + kk] : 0.f;
    }
    __syncthreads();
    float acc[8] = {0.f,0.f,0.f,0.f,0.f,0.f,0.f,0.f};
    #pragma unroll 4
    for (int k = 0; k < FD; k++) {
        float w = g_Wt[k * G4 + g];
        #pragma unroll
        for (int tt = 0; tt < 8; tt++) acc[tt] = fmaf(fs[tt][k], w, acc[tt]);
    }
    float scale = ((g >> 8) == 2) ? -2.8853900817779268f : -1.4426950408889634f;
    #pragma unroll
    for (int tt = 0; tt < 8; tt++) {
        int t = t0 + tt;
        if (t < NFSZ) g_Gf[t * G4 + g] = acc[tt] * scale;
    }
}

// ---------------- main systolic LSTM kernel ----------------
// One CTA per batch element. 3 warpgroups = 3 layers, pipelined systolically.
// Per tick: full 5-level shfl butterfly -> 4 partials/layer (one per warp) in
// parity-buffered smem; one __syncthreads per tick. Cell state pre-scaled:
// cs = 2*log2(e)*c.

#define KK 2.8853900817779268f   /* 2*log2(e) */

__global__ __launch_bounds__(384, 1) void lstm_kernel(
    const float* __restrict__ x,
    const float* __restrict__ Wih0, const float* __restrict__ Whh0,
    const float* __restrict__ bih0, const float* __restrict__ bhh0,
    const float* __restrict__ Whr0,
    const float* __restrict__ Wih1, const float* __restrict__ Whh1,
    const float* __restrict__ bih1, const float* __restrict__ bhh1,
    const float* __restrict__ Whr1,
    const float* __restrict__ Wih2, const float* __restrict__ Whh2,
    const float* __restrict__ bih2, const float* __restrict__ bhh2,
    const float* __restrict__ Whr2,
    float* __restrict__ out)
{
    __shared__ __align__(16) float part[2][3][4];   // [parity][layer][warp partial]

    const int b    = blockIdx.x;
    const int tid  = threadIdx.x;
    const int wg   = tid >> 7;         // layer id 0..2
    const int wtid = tid & 127;
    const int warp = wtid >> 5;
    const int lane = wtid & 31;
    const int u0   = wtid * 2;         // this thread owns hidden units u0, u0+1

    const float L2E   = 1.4426950408889634f;
    const float NL2E2 = -2.8853900817779268f;

    const float* Whh = (wg == 0) ? Whh0 : (wg == 1) ? Whh1 : Whh2;
    const float* Wih = (wg == 1) ? Wih1 : Wih2;
    const float* bih = (wg == 0) ? bih0 : (wg == 1) ? bih1 : bih2;
    const float* bhh = (wg == 0) ? bhh0 : (wg == 1) ? bhh1 : bhh2;
    const float* Whr = (wg == 0) ? Whr0 : (wg == 1) ? Whr1 : Whr2;

    // j = gate*2 + m : gate 0=i,1=f,2=g,3=o
    float whh_s[8], base_s[8], wih_s[8];
    #pragma unroll
    for (int j = 0; j < 8; j++) {
        int gate = j >> 1;
        int idx  = gate * HSZ + u0 + (j & 1);
        float sc = (gate == 2) ? NL2E2 : -L2E;
        whh_s[j] = Whh[idx] * sc;
        float bias = bih[idx] + bhh[idx];
        if (wg == 0) {
            float acc = bias;   // fold x-side input (batch-constant) + bias
            #pragma unroll
            for (int kk = 0; kk < INCH; kk++)
                acc = fmaf(x[b * INCH + kk], Wih0[idx * INS0 + FD + kk], acc);
            base_s[j] = acc * sc;
            wih_s[j]  = 0.f;
        } else {
            base_s[j] = bias * sc;
            wih_s[j]  = Wih[idx] * sc;
        }
    }
    const float w0 = Whr[u0], w1 = Whr[u0 + 1];
    const float awhr0 = fabsf(w0), awhr1 = fabsf(w1);
    const int   sgn0 = __float_as_int(w0) & 0x80000000;
    const int   sgn1 = __float_as_int(w1) & 0x80000000;
    float cs0 = 0.f, cs1 = 0.f;   // scaled cell state: 2*log2e * c

    if (wtid < 4) { part[0][wg][wtid] = 0.f; part[1][wg][wtid] = 0.f; }
    __syncthreads();

    // Gf double buffers (wg0 only uses them)
    float gA[8], gB[8];
    #pragma unroll
    for (int j = 0; j < 8; j++) { gA[j] = 0.f; gB[j] = 0.f; }
    if (wg == 0) {
        #pragma unroll
        for (int g4 = 0; g4 < 4; g4++) {
            float2 v = *(const float2*)&g_Gf[g4 * HSZ + u0];
            gA[2 * g4] = v.x; gA[2 * g4 + 1] = v.y;
        }
    }

#define TICK(KT, GFC, GFN)                                                        \
    {                                                                             \
        const int k_  = (KT);                                                     \
        const int par = k_ & 1, rp = par ^ 1;                                     \
        const int t   = k_ - wg;                                                  \
        /* prefetch next Gf row (layer 0) */                                      \
        if (wg == 0 && (t + 1) < NFSZ) {                                          \
            const float* gp = &g_Gf[(t + 1) * G4];                                \
            _Pragma("unroll")                                                     \
            for (int g4 = 0; g4 < 4; g4++) {                                      \
                float2 v = *(const float2*)(gp + g4 * HSZ + u0);                  \
                GFN[2 * g4] = v.x; GFN[2 * g4 + 1] = v.y;                         \
            }                                                                     \
        }                                                                         \
        float4 own = *(const float4*)part[rp][wg];                                \
        float h_prev = (own.x + own.y) + (own.z + own.w);                         \
        float u_in = 0.f;                                                         \
        if (wg > 0) {                                                             \
            float4 up = *(const float4*)part[rp][wg - 1];                         \
            u_in = (up.x + up.y) + (up.z + up.w);                                 \
        }                                                                         \
        if (wg == 2 && wtid == 0 && k_ >= 3) out[b * NFSZ + (k_ - 3)] = h_prev;   \
        if (t >= 0 && t < NFSZ) {                                                 \
            float pre[8];                                                         \
            if (wg == 0) {                                                        \
                _Pragma("unroll")                                                 \
                for (int j = 0; j < 8; j++)                                       \
                    pre[j] = fmaf(whh_s[j], h_prev, base_s[j] + GFC[j]);          \
            } else {                                                              \
                _Pragma("unroll")                                                 \
                for (int j = 0; j < 8; j++)                                       \
                    pre[j] = fmaf(whh_s[j], h_prev,                               \
                                  fmaf(wih_s[j], u_in, base_s[j]));               \
            }                                                                     \
            float D0, D1, num0, num1, eo0, eo1;                                   \
            {                                                                     \
                float ei = ex2f(pre[0]), ef = ex2f(pre[2]);                       \
                float gs = pre[4];                                                \
                float eg = ex2f(negabsf(gs));                                     \
                eo0 = ex2f(pre[6]);                                               \
                float p1 = 1.f + ei, p2 = 1.f + eg, p3 = 1.f + ef;                \
                float P  = p1 * p2;                                               \
                D0 = P * p3;                                                      \
                float t2 = fmaf(eg, -KK, KK) * p3;                                \
                num0 = fmaf(cs0, P, copysignf(t2, -gs));                          \
            }                                                                     \
            {                                                                     \
                float ei = ex2f(pre[1]), ef = ex2f(pre[3]);                       \
                float gs = pre[5];                                                \
                float eg = ex2f(negabsf(gs));                                     \
                eo1 = ex2f(pre[7]);                                               \
                float p1 = 1.f + ei, p2 = 1.f + eg, p3 = 1.f + ef;                \
                float P  = p1 * p2;                                               \
                D1 = P * p3;                                                      \
                float t2 = fmaf(eg, -KK, KK) * p3;                                \
                num1 = fmaf(cs1, P, copysignf(t2, -gs));                          \
            }                                                                     \
            float R = rcpf(D0 * D1);                                              \
            cs0 = num0 * (R * D1);                                                \
            cs1 = num1 * (R * D0);                                                \
            float ec0 = ex2f(negabsf(cs0));                                       \
            float ec1 = ex2f(negabsf(cs1));                                       \
            float E0 = (1.f + ec0) * (1.f + eo0);                                 \
            float E1 = (1.f + ec1) * (1.f + eo1);                                 \
            float A70 = fmaf(ec0, -awhr0, awhr0);                                 \
            float A71 = fmaf(ec1, -awhr1, awhr1);                                 \
            float R2 = rcpf(E0 * E1);                                             \
            float c0t = A70 * (R2 * E1);                                          \
            float c1t = A71 * (R2 * E0);                                          \
            float s0 = __int_as_float(__float_as_int(cs0) ^ sgn0);                \
            float s1 = __int_as_float(__float_as_int(cs1) ^ sgn1);                \
            float partial = copysignf(c0t, s0) + copysignf(c1t, s1);              \
            partial += __shfl_xor_sync(0xffffffffu, partial, 16);                 \
            partial += __shfl_xor_sync(0xffffffffu, partial, 8);                  \
            partial += __shfl_xor_sync(0xffffffffu, partial, 4);                  \
            partial += __shfl_xor_sync(0xffffffffu, partial, 2);                  \
            partial += __shfl_xor_sync(0xffffffffu, partial, 1);                  \
            if (lane == 0) part[par][wg][warp] = partial;                         \
        }                                                                         \
        __syncthreads();                                                          \
    }

    for (int k = 0; k < NFSZ + 3; k += 2) {   // NFSZ+3 = 1004, even
        TICK(k,     gA, gB)
        TICK(k + 1, gB, gA)
    }
#undef TICK
}

// ---------------- launch ----------------

extern "C" void kernel_launch(void* const* d_in, const int* in_sizes, int n_in,
                              void* d_out, int out_size) {
    const float* x    = (const float*)d_in[0];
    const float* f    = (const float*)d_in[1];
    const float* Wih0 = (const float*)d_in[2];
    const float* Whh0 = (const float*)d_in[3];
    const float* bih0 = (const float*)d_in[4];
    const float* bhh0 = (const float*)d_in[5];
    const float* Whr0 = (const float*)d_in[6];
    const float* Wih1 = (const float*)d_in[7];
    const float* Whh1 = (const float*)d_in[8];
    const float* bih1 = (const float*)d_in[9];
    const float* bhh1 = (const float*)d_in[10];
    const float* Whr1 = (const float*)d_in[11];
    const float* Wih2 = (const float*)d_in[12];
    const float* Whh2 = (const float*)d_in[13];
    const float* bih2 = (const float*)d_in[14];
    const float* bhh2 = (const float*)d_in[15];
    const float* Whr2 = (const float*)d_in[16];

    transpose_kernel<<<512, 256>>>(Wih0);
    gf_kernel<<<dim3(126, 4), 256>>>(f);
    lstm_kernel<<<BSZ, 384>>>(x,
                              Wih0, Whh0, bih0, bhh0, Whr0,
                              Wih1, Whh1, bih1, bhh1, Whr1,
                              Wih2, Whh2, bih2, bhh2, Whr2,
                              (float*)d_out);
}

// round 6
// speedup vs baseline: 1.4946x; 1.4946x over previous
#include <cuda_runtime.h>

#define NFSZ 1001
#define HSZ   256
#define BSZ   64
#define FD    128
#define INCH  16
#define G4    1024   // 4*H
#define INS0  144    // FD + INCH

// scratch (device globals: allocation-free rule; zero-initialized at load)
__device__ float g_Wt[FD * G4];       // transposed f-part of W_ih0
__device__ float g_Gf[NFSZ * G4];     // pre-scaled f-side gate pre-activations
__device__ unsigned long long g_mb[BSZ * 1024];  // layer0->layer1 mailbox {val,flag}

__device__ __forceinline__ float ex2f(float x) {
    float y; asm("ex2.approx.f32 %0, %1;" : "=f"(y) : "f"(x)); return y;
}
__device__ __forceinline__ float rcpf(float x) {
    float y; asm("rcp.approx.f32 %0, %1;" : "=f"(y) : "f"(x)); return y;
}
__device__ __forceinline__ float negabsf(float x) {
    return __int_as_float(__float_as_int(x) | 0x80000000);
}
__device__ __forceinline__ unsigned long long ldv64(const unsigned long long* p) {
    unsigned long long v;
    asm volatile("ld.volatile.global.b64 %0, [%1];" : "=l"(v) : "l"(p));
    return v;
}
__device__ __forceinline__ void stv64(unsigned long long* p, unsigned long long v) {
    asm volatile("st.volatile.global.b64 [%0], %1;" :: "l"(p), "l"(v) : "memory");
}

// ---------------- precompute kernels ----------------

__global__ void transpose_kernel(const float* __restrict__ Wih0) {
    int idx = blockIdx.x * blockDim.x + threadIdx.x;
    if (idx >= FD * G4) return;
    int g = idx / FD;
    int k = idx - g * FD;
    g_Wt[k * G4 + g] = Wih0[g * INS0 + k];
}

__global__ void gf_kernel(const float* __restrict__ f) {
    __shared__ float fs[8][FD];
    int tx = threadIdx.x;
    int g  = blockIdx.y * 256 + tx;
    int t0 = blockIdx.x * 8;
    #pragma unroll
    for (int i = 0; i < 4; i++) {
        int e  = tx + i * 256;
        int tt = e >> 7, kk = e & 127;
        int t  = t0 + tt;
        fs[tt][kk] = (t < NFSZ) ? f[t * FD + kk] : 0.f;
    }
    __syncthreads();
    float acc[8] = {0.f,0.f,0.f,0.f,0.f,0.f,0.f,0.f};
    #pragma unroll 4
    for (int k = 0; k < FD; k++) {
        float w = g_Wt[k * G4 + g];
        #pragma unroll
        for (int tt = 0; tt < 8; tt++) acc[tt] = fmaf(fs[tt][k], w, acc[tt]);
    }
    float scale = ((g >> 8) == 2) ? -2.8853900817779268f : -1.4426950408889634f;
    #pragma unroll
    for (int tt = 0; tt < 8; tt++) {
        int t = t0 + tt;
        if (t < NFSZ) g_Gf[t * G4 + g] = acc[tt] * scale;
    }
}

// ---------------- main LSTM kernel: 2 CTAs per batch ----------------
// blockIdx.x even -> role A (layer 0, 256 thr, 1 unit/thread)
// blockIdx.x odd  -> role B (layers 1+2 as two warpgroups, 2 units/thread)
// A->B link: gmem mailbox with 3-tick skew (prefetched, off-chain).
// B-internal layer1->layer2 link: smem scalar, 2-tick relative skew.

#define L2E   1.4426950408889634f
#define NL2E2 -2.8853900817779268f

__global__ __launch_bounds__(256, 1) void lstm_kernel(
    const float* __restrict__ x,
    const float* __restrict__ Wih0, const float* __restrict__ Whh0,
    const float* __restrict__ bih0, const float* __restrict__ bhh0,
    const float* __restrict__ Whr0,
    const float* __restrict__ Wih1, const float* __restrict__ Whh1,
    const float* __restrict__ bih1, const float* __restrict__ bhh1,
    const float* __restrict__ Whr1,
    const float* __restrict__ Wih2, const float* __restrict__ Whh2,
    const float* __restrict__ bih2, const float* __restrict__ bhh2,
    const float* __restrict__ Whr2,
    float* __restrict__ out)
{
    __shared__ __align__(16) float partA[2][8];      // role A: one partial per warp
    __shared__ __align__(16) float partB[2][2][16];  // role B: [parity][layer][16]
    __shared__ float fwdB[2];                        // layer1 -> layer2 scalar

    const int b    = blockIdx.x >> 1;
    const int role = blockIdx.x & 1;
    const int tid  = threadIdx.x;

    if (role == 0) {
        // ================= ROLE A : layer 0, 1 unit per thread =================
        const int u    = tid;
        const int warp = tid >> 5;
        const int lane = tid & 31;

        float whh_s[4], base_s[4];
        #pragma unroll
        for (int g = 0; g < 4; g++) {
            int idx  = g * HSZ + u;
            float sc = (g == 2) ? NL2E2 : -L2E;
            whh_s[g] = Whh0[idx] * sc;
            float acc = bih0[idx] + bhh0[idx];
            #pragma unroll
            for (int kk = 0; kk < INCH; kk++)
                acc = fmaf(x[b * INCH + kk], Wih0[idx * INS0 + FD + kk], acc);
            base_s[g] = acc * sc;
        }
        const float whr = Whr0[u];
        float c = 0.f;

        if (tid < 8)  { partA[0][tid] = 0.f; partA[1][tid] = 0.f; }
        __syncthreads();

        // Gf double buffer (gate g for unit u at row t: g_Gf[t*G4 + g*HSZ + u])
        float gfc[4], gfn[4];
        #pragma unroll
        for (int g = 0; g < 4; g++) gfc[g] = g_Gf[g * HSZ + u] + base_s[g];

        unsigned long long* mb = &g_mb[b * 1024];

        for (int k = 0; k <= NFSZ; k++) {
            const int par = k & 1, rp = par ^ 1;
            // prefetch next Gf row, pre-added with base (off-chain)
            if (k + 1 <= NFSZ - 1) {
                const float* gp = &g_Gf[(k + 1) * G4 + u];
                #pragma unroll
                for (int g = 0; g < 4; g++) gfn[g] = gp[g * HSZ] + base_s[g];
            }
            // h_prev = output(k-1): sum 8 warp partials
            float4 p0 = *(const float4*)&partA[rp][0];
            float4 p1 = *(const float4*)&partA[rp][4];
            float h_prev = ((p0.x + p0.y) + (p0.z + p0.w))
                         + ((p1.x + p1.y) + (p1.z + p1.w));
            if (k >= 1 && tid == 0) {
                unsigned long long pk =
                    (unsigned long long)(unsigned)__float_as_int(h_prev)
                    | ((unsigned long long)(unsigned)k << 32);   // flag = (k-1)+1
                stv64(&mb[k - 1], pk);
            }
            if (k <= NFSZ - 1) {
                float pre0 = fmaf(whh_s[0], h_prev, gfc[0]);
                float pre1 = fmaf(whh_s[1], h_prev, gfc[1]);
                float pre2 = fmaf(whh_s[2], h_prev, gfc[2]);
                float pre3 = fmaf(whh_s[3], h_prev, gfc[3]);
                float ei = ex2f(pre0), ef = ex2f(pre1);
                float gs = pre2;
                float eg = ex2f(negabsf(gs));
                float eo = ex2f(pre3);
                float sf  = rcpf(1.f + ef);
                float mag = (1.f - eg) * rcpf((1.f + ei) * (1.f + eg));
                float itg = copysignf(mag, -gs);
                c = fmaf(sf, c, itg);
                float ec = ex2f(NL2E2 * fabsf(c));
                float hm = (1.f - ec) * rcpf((1.f + eo) * (1.f + ec));
                float hr = copysignf(hm, c);
                float partial = hr * whr;
                partial += __shfl_xor_sync(0xffffffffu, partial, 16);
                partial += __shfl_xor_sync(0xffffffffu, partial, 8);
                partial += __shfl_xor_sync(0xffffffffu, partial, 4);
                partial += __shfl_xor_sync(0xffffffffu, partial, 2);
                partial += __shfl_xor_sync(0xffffffffu, partial, 1);
                if (lane == 0) partA[par][warp] = partial;
            }
            #pragma unroll
            for (int g = 0; g < 4; g++) gfc[g] = gfn[g];
            __syncthreads();
        }
    } else {
        // ============ ROLE B : layers 1 (wg0, t=k-3) + 2 (wg1, t=k-5) ============
        const int wg   = tid >> 7;          // 0 -> layer1, 1 -> layer2
        const int wtid = tid & 127;
        const int warp = wtid >> 5;
        const int lane = wtid & 31;
        const int u0   = wtid * 2;

        const float* Whh = wg ? Whh2 : Whh1;
        const float* Wih = wg ? Wih2 : Wih1;
        const float* bih = wg ? bih2 : bih1;
        const float* bhh = wg ? bhh2 : bhh1;
        const float* Whr = wg ? Whr2 : Whr1;
        const int skew = wg ? 5 : 3;

        float whh_s[8], base_s[8], wih_s[8];
        #pragma unroll
        for (int j = 0; j < 8; j++) {
            int gate = j >> 1;
            int idx  = gate * HSZ + u0 + (j & 1);
            float sc = (gate == 2) ? NL2E2 : -L2E;
            whh_s[j]  = Whh[idx] * sc;
            base_s[j] = (bih[idx] + bhh[idx]) * sc;
            wih_s[j]  = Wih[idx] * sc;
        }
        const float whr0v = Whr[u0], whr1v = Whr[u0 + 1];
        float c0 = 0.f, c1 = 0.f;

        if (wtid < 16) { partB[0][wg][wtid] = 0.f; partB[1][wg][wtid] = 0.f; }
        if (tid < 2)   fwdB[tid] = 0.f;
        __syncthreads();

        unsigned long long* mb = &g_mb[b * 1024];
        unsigned long long mv = 0;   // prefetched mailbox word (layer1 only)

        for (int k = 0; k <= NFSZ + 5; k++) {
            const int par = k & 1, rp = par ^ 1;
            const int t = k - skew;
            const bool active = (t >= 0) && (t < NFSZ);

            // own h_prev: sum 16 partials
            float h_prev;
            {
                const float4* p = (const float4*)partB[rp][wg];
                float4 a = p[0], q = p[1], r = p[2], d = p[3];
                h_prev = (((a.x + a.y) + (a.z + a.w)) + ((q.x + q.y) + (q.z + q.w)))
                       + (((r.x + r.y) + (r.z + r.w)) + ((d.x + d.y) + (d.z + d.w)));
            }
            // inter-layer input scalar
            float u_in = 0.f;
            if (wg == 0) {
                if (active) {
                    unsigned exp_flag = (unsigned)(t + 1);
                    while ((unsigned)(mv >> 32) != exp_flag) mv = ldv64(&mb[t]);
                    u_in = __int_as_float((int)(unsigned)mv);
                }
                // layer1 forwards its materialized output(t-1) to layer2
                if (wtid == 0) fwdB[par] = h_prev;
            } else {
                u_in = fwdB[rp];
                if (wtid == 0 && k >= 6) out[b * NFSZ + (k - 6)] = h_prev;
            }

            if (active) {
                float pre[8];
                #pragma unroll
                for (int j = 0; j < 8; j++)
                    pre[j] = fmaf(whh_s[j], h_prev, fmaf(wih_s[j], u_in, base_s[j]));
                float partial = 0.f;
                #pragma unroll
                for (int m = 0; m < 2; m++) {
                    float ei = ex2f(pre[m]);
                    float ef = ex2f(pre[2 + m]);
                    float gs = pre[4 + m];
                    float eg = ex2f(negabsf(gs));
                    float eo = ex2f(pre[6 + m]);
                    float sf  = rcpf(1.f + ef);
                    float mag = (1.f - eg) * rcpf((1.f + ei) * (1.f + eg));
                    float itg = copysignf(mag, -gs);
                    float c = (m == 0) ? c0 : c1;
                    c = fmaf(sf, c, itg);
                    float ec = ex2f(NL2E2 * fabsf(c));
                    float hm = (1.f - ec) * rcpf((1.f + eo) * (1.f + ec));
                    float hr = copysignf(hm, c);
                    if (m == 0) { c0 = c; partial = fmaf(hr, whr0v, partial); }
                    else        { c1 = c; partial = fmaf(hr, whr1v, partial); }
                }
                partial += __shfl_xor_sync(0xffffffffu, partial, 16);
                partial += __shfl_xor_sync(0xffffffffu, partial, 8);
                partial += __shfl_xor_sync(0xffffffffu, partial, 4);
                if (lane < 4) partB[par][wg][warp * 4 + lane] = partial;
            }
            // layer1: prefetch next tick's mailbox word (off-chain; spin at use)
            if (wg == 0) {
                int tn = t + 1;
                if (tn >= 0 && tn < NFSZ) mv = ldv64(&mb[tn]);
            }
            __syncthreads();
        }
    }
}

// ---------------- launch ----------------

extern "C" void kernel_launch(void* const* d_in, const int* in_sizes, int n_in,
                              void* d_out, int out_size) {
    const float* x    = (const float*)d_in[0];
    const float* f    = (const float*)d_in[1];
    const float* Wih0 = (const float*)d_in[2];
    const float* Whh0 = (const float*)d_in[3];
    const float* bih0 = (const float*)d_in[4];
    const float* bhh0 = (const float*)d_in[5];
    const float* Whr0 = (const float*)d_in[6];
    const float* Wih1 = (const float*)d_in[7];
    const float* Whh1 = (const float*)d_in[8];
    const float* bih1 = (const float*)d_in[9];
    const float* bhh1 = (const float*)d_in[10];
    const float* Whr1 = (const float*)d_in[11];
    const float* Wih2 = (const float*)d_in[12];
    const float* Whh2 = (const float*)d_in[13];
    const float* bih2 = (const float*)d_in[14];
    const float* bhh2 = (const float*)d_in[15];
    const float* Whr2 = (const float*)d_in[16];

    transpose_kernel<<<512, 256>>>(Wih0);
    gf_kernel<<<dim3(126, 4), 256>>>(f);
    lstm_kernel<<<2 * BSZ, 256>>>(x,
                                  Wih0, Whh0, bih0, bhh0, Whr0,
                                  Wih1, Whh1, bih1, bhh1, Whr1,
                                  Wih2, Whh2, bih2, bhh2, Whr2,
                                  (float*)d_out);
}